// round 15
// baseline (speedup 1.0000x reference)
#include <cuda_runtime.h>
#include <cuda_bf16.h>
#include <cstdint>

// ============================================================================
// NeuralODE persistent mma.sync kernel, round 13
// (R12 winner + non-volatile mma for ptxas scheduling freedom + KCACHE=7).
// 128 CTAs x 32 rows. Per step:
//   stage1: H1 = tanh(X@W1+b1)  (W1 B-frags in regs; tanh.approx.bf16x2)
//   stage2: acc2 = H1@W2        (first 7 ks B-frags cached in regs,
//                                rest double-buffered via ldmatrix)
//   stage3: fused tanh(bf16x2)->A-frags, partial F = H2_w @ W3_slice in regs,
//           bf16 partials reduced 8-way in smem with bf16x2 tree adds.
//   Euler update + trajectory from fragment-resident fp32 state.
// ============================================================================

#define STATE     64
#define HID       256
#define BATCHN    4096
#define MROWS     32
#define NCTAS     (BATCHN / MROWS)   // 128
#define NTHREADS  256
#define KCACHE    7                  // W2 k-steps cached in registers

// ---- smem strides; (stride/16) odd -> ldmatrix conflict-free ----
#define W2_STR 528
#define W1_STR 144
#define W3_STR 528
#define XB_STR 144
#define H_STR  528
#define RROW_STR 144
#define RW_STR  4608      // per-warp partial block: 32 rows x 144

#define W2_OFF 0u          // 135168
#define XB_OFF 135168u     //   4608 -> 139776
#define H1_OFF 139776u     //  16896 -> 156672   (also transient W1/W3 staging)
#define RED_OFF 156672u    //  36864 -> 193536
#define B1S_OFF 193536u
#define B2S_OFF 194560u
#define B3S_OFF 195584u
#define SMEM_BYTES 195840u

// ============================================================================
// helpers
// ============================================================================
static __device__ __forceinline__ uint32_t smem_u32(const void* p) {
    uint32_t a;
    asm("{ .reg .u64 t; cvta.to.shared.u64 t, %1; cvt.u32.u64 %0, t; }"
        : "=r"(a) : "l"(p));
    return a;
}

static __device__ __forceinline__ uint32_t pack_bf16x2(float lo, float hi) {
    uint32_t p;
    asm("cvt.rn.bf16x2.f32 %0, %1, %2;" : "=r"(p) : "f"(hi), "f"(lo));
    return p;
}

// elementwise tanh on a bf16x2 pair — ONE MUFU op for two activations
static __device__ __forceinline__ uint32_t tanh_bf16x2(uint32_t a) {
    uint32_t d;
    asm("tanh.approx.bf16x2 %0, %1;" : "=r"(d) : "r"(a));
    return d;
}

static __device__ __forceinline__ uint32_t hadd2_bf16(uint32_t a, uint32_t b) {
    uint32_t d;
    asm("add.rn.bf16x2 %0, %1, %2;" : "=r"(d) : "r"(a), "r"(b));
    return d;
}

static __device__ __forceinline__ float bf16lo(uint32_t u) {
    return __uint_as_float(u << 16);
}
static __device__ __forceinline__ float bf16hi(uint32_t u) {
    return __uint_as_float(u & 0xFFFF0000u);
}

static __device__ __forceinline__ void ldm_x4(uint32_t* r, uint32_t addr) {
    asm volatile("ldmatrix.sync.aligned.m8n8.x4.shared.b16 {%0,%1,%2,%3}, [%4];"
                 : "=r"(r[0]), "=r"(r[1]), "=r"(r[2]), "=r"(r[3]) : "r"(addr));
}

// NOTE: intentionally NOT volatile — mma has pure register semantics, so data
// dependences fully constrain it; this lets ptxas software-pipeline the mma
// stream against ldmatrix returns and epilogue code.
static __device__ __forceinline__ void mma_bf16(float* d, const uint32_t* a,
                                                const uint32_t* b) {
    asm("mma.sync.aligned.m16n8k16.row.col.f32.bf16.bf16.f32 "
        "{%0,%1,%2,%3}, {%4,%5,%6,%7}, {%8,%9}, {%0,%1,%2,%3};"
        : "+f"(d[0]), "+f"(d[1]), "+f"(d[2]), "+f"(d[3])
        : "r"(a[0]), "r"(a[1]), "r"(a[2]), "r"(a[3]), "r"(b[0]), "r"(b[1]));
}

// ============================================================================
// Kernel
// ============================================================================
__global__ void __launch_bounds__(NTHREADS, 1)
neural_ode_kernel(const float* __restrict__ x0, const float* __restrict__ W1,
                  const float* __restrict__ b1, const float* __restrict__ W2,
                  const float* __restrict__ b2, const float* __restrict__ W3,
                  const float* __restrict__ b3, const float* __restrict__ dts,
                  float* __restrict__ out, int T)
{
    extern __shared__ char smem[];
    const uint32_t sb = smem_u32(smem);
    const int tid = threadIdx.x;
    const int wid = tid >> 5;
    const int lane = tid & 31;
    const int nb = wid * 32;
    const uint32_t q = (uint32_t)(lane >> 3), r = (uint32_t)(lane & 7);

    // ---- stage W2 (permanent) + W1 (transient at H1_OFF) + biases ----
    for (int i = tid; i < HID * HID; i += NTHREADS) {            // W2 [256k][256n]
        int k = i >> 8, n = i & 255;
        *reinterpret_cast<__nv_bfloat16*>(smem + W2_OFF + (uint32_t)n * W2_STR
                                          + (uint32_t)k * 2u) = __float2bfloat16(W2[i]);
    }
    for (int i = tid; i < STATE * HID; i += NTHREADS) {          // W1 [64k][256n]
        int k = i >> 8, n = i & 255;
        *reinterpret_cast<__nv_bfloat16*>(smem + H1_OFF + (uint32_t)n * W1_STR
                                          + (uint32_t)k * 2u) = __float2bfloat16(W1[i]);
    }
    float* b1s = reinterpret_cast<float*>(smem + B1S_OFF);
    float* b2s = reinterpret_cast<float*>(smem + B2S_OFF);
    float* b3s = reinterpret_cast<float*>(smem + B3S_OFF);
    for (int i = tid; i < HID; i += NTHREADS) { b1s[i] = b1[i]; b2s[i] = b2[i]; }
    for (int i = tid; i < STATE; i += NTHREADS) b3s[i] = b3[i];
    __syncthreads();

    // ---- preload W1 B-fragments: warp w, n-cols 32w..32w+32, all K=64 ----
    uint32_t b1r[32];   // [ks*8 + {b01[0..3], b23[0..3]}]
    {
        const uint32_t bb = sb + H1_OFF
                          + (uint32_t)(nb + (int)((q >> 1) * 8) + (int)r) * W1_STR
                          + (q & 1) * 16u;
        #pragma unroll
        for (int ks = 0; ks < 4; ks++) {
            ldm_x4(b1r + ks * 8,     bb + (uint32_t)ks * 32u);
            ldm_x4(b1r + ks * 8 + 4, bb + 16u * W1_STR + (uint32_t)ks * 32u);
        }
    }
    __syncthreads();

    // ---- stage W3^T [64 n3][256 k] transient at H1_OFF; init x/traj/XB ----
    for (int i = tid; i < HID * STATE; i += NTHREADS) {
        int k = i >> 6, n = i & 63;
        *reinterpret_cast<__nv_bfloat16*>(smem + H1_OFF + (uint32_t)n * W3_STR
                                          + (uint32_t)k * 2u) = __float2bfloat16(W3[i]);
    }

    const float dtdt = dts[0] * 0.01f;
    const int nsteps = T - 1;
    const int gb = blockIdx.x * MROWS;
    const int colb = wid * 8 + 2 * (lane & 3);

    float xr[2][4];   // D-fragment-resident fp32 state
    #pragma unroll
    for (int mt = 0; mt < 2; mt++)
        #pragma unroll
        for (int half = 0; half < 2; half++) {
            const int row = mt * 16 + half * 8 + (lane >> 2);
            const float2 v = *reinterpret_cast<const float2*>(
                x0 + (size_t)(gb + row) * STATE + colb);
            xr[mt][2 * half] = v.x;
            xr[mt][2 * half + 1] = v.y;
            *reinterpret_cast<float2*>(
                out + (size_t)(gb + row) * T * STATE + colb) = v;
            *reinterpret_cast<uint32_t*>(smem + XB_OFF + (uint32_t)row * XB_STR
                + (uint32_t)colb * 2u) = pack_bf16x2(v.x, v.y);
        }
    __syncthreads();

    // ---- preload W3 B-fragments: warp w's k-slice [32w,32w+32), all 64 n3 ----
    uint32_t b3r[32];   // [nt3*4 + {kc0: 0,1 | kc1: 2,3}]
    {
        const uint32_t bb = sb + H1_OFF + r * W3_STR + (uint32_t)(wid * 64) + q * 16u;
        #pragma unroll
        for (int nt3 = 0; nt3 < 8; nt3++)
            ldm_x4(b3r + nt3 * 4, bb + (uint32_t)(nt3 * 8) * W3_STR);
    }
    __syncthreads();

    const uint32_t b2base = sb + W2_OFF
                          + (uint32_t)(nb + (int)((q >> 1) * 8) + (int)r) * W2_STR
                          + (q & 1) * 16u;
    const float bb3_0 = b3s[colb], bb3_1 = b3s[colb + 1];

    // ---- cache first KCACHE k-steps of W2 B-fragments (loop-invariant) ----
    uint32_t b2c[KCACHE * 8];
    #pragma unroll
    for (int ks = 0; ks < KCACHE; ks++) {
        ldm_x4(b2c + ks * 8,     b2base + (uint32_t)ks * 32u);
        ldm_x4(b2c + ks * 8 + 4, b2base + 16u * W2_STR + (uint32_t)ks * 32u);
    }

    for (int s = 0; s < nsteps; s++) {
        // ====== stage 1: H1 = tanh(X@W1+b1), B in regs, bf16x2 tanh ========
        {
            float acc[2][4][4];
            #pragma unroll
            for (int i = 0; i < 2; i++)
                #pragma unroll
                for (int j = 0; j < 4; j++)
                    #pragma unroll
                    for (int c = 0; c < 4; c++) acc[i][j][c] = 0.f;

            const uint32_t a_base = sb + XB_OFF + (uint32_t)(lane & 15) * XB_STR
                                  + (uint32_t)(lane >> 4) * 16u;
            #pragma unroll
            for (int ks = 0; ks < 4; ks++) {
                uint32_t a0[4], a1[4];
                ldm_x4(a0, a_base + (uint32_t)ks * 32u);
                ldm_x4(a1, a_base + 16u * XB_STR + (uint32_t)ks * 32u);
                const uint32_t* bk = b1r + ks * 8;
                mma_bf16(acc[0][0], a0, bk + 0);
                mma_bf16(acc[0][1], a0, bk + 2);
                mma_bf16(acc[0][2], a0, bk + 4);
                mma_bf16(acc[0][3], a0, bk + 6);
                mma_bf16(acc[1][0], a1, bk + 0);
                mma_bf16(acc[1][1], a1, bk + 2);
                mma_bf16(acc[1][2], a1, bk + 4);
                mma_bf16(acc[1][3], a1, bk + 6);
            }
            #pragma unroll
            for (int mt = 0; mt < 2; mt++) {
                const int row = mt * 16 + (lane >> 2);
                #pragma unroll
                for (int nt = 0; nt < 4; nt++) {
                    const int col = nb + nt * 8 + 2 * (lane & 3);
                    const float c0 = b1s[col], c1 = b1s[col + 1];
                    uint32_t t01 = tanh_bf16x2(pack_bf16x2(acc[mt][nt][0] + c0,
                                                           acc[mt][nt][1] + c1));
                    uint32_t t23 = tanh_bf16x2(pack_bf16x2(acc[mt][nt][2] + c0,
                                                           acc[mt][nt][3] + c1));
                    *reinterpret_cast<uint32_t*>(smem + H1_OFF + (uint32_t)row * H_STR
                        + (uint32_t)col * 2u) = t01;
                    *reinterpret_cast<uint32_t*>(smem + H1_OFF + (uint32_t)(row + 8) * H_STR
                        + (uint32_t)col * 2u) = t23;
                }
            }
        }

        // prefetch B2 for the first UNCACHED ks before the barrier (W2 static)
        uint32_t bcur[8];
        ldm_x4(bcur,     b2base + (uint32_t)KCACHE * 32u);
        ldm_x4(bcur + 4, b2base + 16u * W2_STR + (uint32_t)KCACHE * 32u);
        __syncthreads();                              // H1 visible

        // ====== stage 2: acc2 = H1 @ W2 (K=256), B partly cached ===========
        float acc2[2][4][4];
        #pragma unroll
        for (int i = 0; i < 2; i++)
            #pragma unroll
            for (int j = 0; j < 4; j++)
                #pragma unroll
                for (int c = 0; c < 4; c++) acc2[i][j][c] = 0.f;
        {
            const uint32_t a_base = sb + H1_OFF + (uint32_t)(lane & 15) * H_STR
                                  + (uint32_t)(lane >> 4) * 16u;
            uint32_t ac[8];
            ldm_x4(ac,     a_base);
            ldm_x4(ac + 4, a_base + 16u * H_STR);
            #pragma unroll
            for (int ks = 0; ks < 16; ks++) {
                uint32_t an[8], bn[8];
                if (ks < 15) {
                    ldm_x4(an,     a_base + (uint32_t)(ks + 1) * 32u);
                    ldm_x4(an + 4, a_base + 16u * H_STR + (uint32_t)(ks + 1) * 32u);
                }
                const bool cached = (ks < KCACHE);
                if (!cached && ks < 15) {             // prefetch next uncached B
                    ldm_x4(bn,     b2base + (uint32_t)(ks + 1) * 32u);
                    ldm_x4(bn + 4, b2base + 16u * W2_STR + (uint32_t)(ks + 1) * 32u);
                }
                const uint32_t* bp = cached ? (b2c + ks * 8) : bcur;
                mma_bf16(acc2[0][0], ac,     bp + 0);
                mma_bf16(acc2[0][1], ac,     bp + 2);
                mma_bf16(acc2[0][2], ac,     bp + 4);
                mma_bf16(acc2[0][3], ac,     bp + 6);
                mma_bf16(acc2[1][0], ac + 4, bp + 0);
                mma_bf16(acc2[1][1], ac + 4, bp + 2);
                mma_bf16(acc2[1][2], ac + 4, bp + 4);
                mma_bf16(acc2[1][3], ac + 4, bp + 6);
                if (ks < 15) {
                    #pragma unroll
                    for (int t = 0; t < 8; t++) ac[t] = an[t];
                    if (!cached) {
                        #pragma unroll
                        for (int t = 0; t < 8; t++) bcur[t] = bn[t];
                    }
                }
            }
        }

        // ======= fused stage 3: bf16x2 tanh -> A-frags -> partial F ========
        {
            uint32_t p[2][4][2];   // tanh(H2) packed bf16x2; [mt][nt][half-row]
            #pragma unroll
            for (int mt = 0; mt < 2; mt++)
                #pragma unroll
                for (int nt = 0; nt < 4; nt++) {
                    const int col = nb + nt * 8 + 2 * (lane & 3);
                    const float c0 = b2s[col], c1 = b2s[col + 1];
                    p[mt][nt][0] = tanh_bf16x2(pack_bf16x2(acc2[mt][nt][0] + c0,
                                                           acc2[mt][nt][1] + c1));
                    p[mt][nt][1] = tanh_bf16x2(pack_bf16x2(acc2[mt][nt][2] + c0,
                                                           acc2[mt][nt][3] + c1));
                }

            const uint32_t rbo = RED_OFF + (uint32_t)wid * RW_STR
                               + (uint32_t)(2 * (lane & 3)) * 2u
                               + (uint32_t)(lane >> 2) * RROW_STR;

            #pragma unroll
            for (int mt = 0; mt < 2; mt++) {
                float f3[8][4];
                #pragma unroll
                for (int nt3 = 0; nt3 < 8; nt3++)
                    #pragma unroll
                    for (int c = 0; c < 4; c++) f3[nt3][c] = 0.f;
                #pragma unroll
                for (int kc = 0; kc < 2; kc++) {
                    uint32_t af[4] = { p[mt][2 * kc][0], p[mt][2 * kc][1],
                                       p[mt][2 * kc + 1][0], p[mt][2 * kc + 1][1] };
                    #pragma unroll
                    for (int nt3 = 0; nt3 < 8; nt3++)
                        mma_bf16(f3[nt3], af, b3r + nt3 * 4 + kc * 2);
                }
                #pragma unroll
                for (int nt3 = 0; nt3 < 8; nt3++) {
                    const uint32_t cb = (uint32_t)(nt3 * 8) * 2u
                                      + (uint32_t)(mt * 16) * RROW_STR;
                    *reinterpret_cast<uint32_t*>(smem + rbo + cb)
                        = pack_bf16x2(f3[nt3][0], f3[nt3][1]);
                    *reinterpret_cast<uint32_t*>(smem + rbo + cb + 8u * RROW_STR)
                        = pack_bf16x2(f3[nt3][2], f3[nt3][3]);
                }
            }
        }
        __syncthreads();                              // partials ready

        // ====== reduce 8 partials (bf16x2 tree) + Euler + traj + XB ========
        #pragma unroll
        for (int mt = 0; mt < 2; mt++)
            #pragma unroll
            for (int half = 0; half < 2; half++) {
                const int row = mt * 16 + half * 8 + (lane >> 2);
                const uint32_t a0 = RED_OFF + (uint32_t)row * RROW_STR
                                  + (uint32_t)colb * 2u;
                uint32_t u[8];
                #pragma unroll
                for (int w2 = 0; w2 < 8; w2++)
                    u[w2] = *reinterpret_cast<const uint32_t*>(
                        smem + a0 + (uint32_t)w2 * RW_STR);
                uint32_t t0 = hadd2_bf16(hadd2_bf16(u[0], u[1]),
                                         hadd2_bf16(u[2], u[3]));
                uint32_t t1 = hadd2_bf16(hadd2_bf16(u[4], u[5]),
                                         hadd2_bf16(u[6], u[7]));
                float s0 = bf16lo(t0) + bf16lo(t1);
                float s1 = bf16hi(t0) + bf16hi(t1);
                float xa = fmaf(s0 + bb3_0, dtdt, xr[mt][2 * half]);
                float xb = fmaf(s1 + bb3_1, dtdt, xr[mt][2 * half + 1]);
                xr[mt][2 * half] = xa;
                xr[mt][2 * half + 1] = xb;
                // gmem trajectory first (no consumer -> issue early),
                // then the XB smem store for next step
                *reinterpret_cast<float2*>(
                    out + ((size_t)(gb + row) * T + (size_t)(s + 1)) * STATE + colb)
                    = make_float2(xa, xb);
                *reinterpret_cast<uint32_t*>(smem + XB_OFF + (uint32_t)row * XB_STR
                    + (uint32_t)colb * 2u) = pack_bf16x2(xa, xb);
            }
        __syncthreads();                              // XB ready, RED consumed
    }
}

// ============================================================================
// Launch
// ============================================================================
extern "C" void kernel_launch(void* const* d_in, const int* in_sizes, int n_in,
                              void* d_out, int out_size) {
    const float* x0  = (const float*)d_in[0];
    const float* W1  = (const float*)d_in[1];
    const float* b1  = (const float*)d_in[2];
    const float* W2  = (const float*)d_in[3];
    const float* b2  = (const float*)d_in[4];
    const float* W3  = (const float*)d_in[5];
    const float* b3  = (const float*)d_in[6];
    const float* dts = (const float*)d_in[7];
    float* out = (float*)d_out;

    const int T = out_size / (BATCHN * STATE);   // steps + 1

    cudaFuncSetAttribute(neural_ode_kernel,
                         cudaFuncAttributeMaxDynamicSharedMemorySize, SMEM_BYTES);
    neural_ode_kernel<<<NCTAS, NTHREADS, SMEM_BYTES>>>(
        x0, W1, b1, W2, b2, W3, b3, dts, out, T);
}

// round 16
// speedup vs baseline: 1.0263x; 1.0263x over previous
#include <cuda_runtime.h>
#include <cuda_bf16.h>
#include <cstdint>

// ============================================================================
// NeuralODE persistent mma.sync kernel, round 15
// (R12 winner + zero-copy ping-pong double buffering in stage 2).
// 128 CTAs x 32 rows. Per step:
//   stage1: H1 = tanh(X@W1+b1)  (W1 B-frags in regs; tanh.approx.bf16x2)
//   stage2: acc2 = H1@W2        (first 6 ks B-frags cached in regs; remaining
//                                A/B fragments ping-pong double-buffered, no MOVs)
//   stage3: fused tanh(bf16x2)->A-frags, partial F = H2_w @ W3_slice in regs,
//           bf16 partials reduced 8-way in smem with bf16x2 tree adds.
//   Euler update + trajectory from fragment-resident fp32 state.
// ============================================================================

#define STATE     64
#define HID       256
#define BATCHN    4096
#define MROWS     32
#define NCTAS     (BATCHN / MROWS)   // 128
#define NTHREADS  256
#define KCACHE    6                  // W2 k-steps cached in registers (EVEN)

// ---- smem strides; (stride/16) odd -> ldmatrix conflict-free ----
#define W2_STR 528
#define W1_STR 144
#define W3_STR 528
#define XB_STR 144
#define H_STR  528
#define RROW_STR 144
#define RW_STR  4608      // per-warp partial block: 32 rows x 144

#define W2_OFF 0u          // 135168
#define XB_OFF 135168u     //   4608 -> 139776
#define H1_OFF 139776u     //  16896 -> 156672   (also transient W1/W3 staging)
#define RED_OFF 156672u    //  36864 -> 193536
#define B1S_OFF 193536u
#define B2S_OFF 194560u
#define B3S_OFF 195584u
#define SMEM_BYTES 195840u

// ============================================================================
// helpers
// ============================================================================
static __device__ __forceinline__ uint32_t smem_u32(const void* p) {
    uint32_t a;
    asm("{ .reg .u64 t; cvta.to.shared.u64 t, %1; cvt.u32.u64 %0, t; }"
        : "=r"(a) : "l"(p));
    return a;
}

static __device__ __forceinline__ uint32_t pack_bf16x2(float lo, float hi) {
    uint32_t p;
    asm("cvt.rn.bf16x2.f32 %0, %1, %2;" : "=r"(p) : "f"(hi), "f"(lo));
    return p;
}

// elementwise tanh on a bf16x2 pair — ONE MUFU op for two activations
static __device__ __forceinline__ uint32_t tanh_bf16x2(uint32_t a) {
    uint32_t d;
    asm("tanh.approx.bf16x2 %0, %1;" : "=r"(d) : "r"(a));
    return d;
}

static __device__ __forceinline__ uint32_t hadd2_bf16(uint32_t a, uint32_t b) {
    uint32_t d;
    asm("add.rn.bf16x2 %0, %1, %2;" : "=r"(d) : "r"(a), "r"(b));
    return d;
}

static __device__ __forceinline__ float bf16lo(uint32_t u) {
    return __uint_as_float(u << 16);
}
static __device__ __forceinline__ float bf16hi(uint32_t u) {
    return __uint_as_float(u & 0xFFFF0000u);
}

static __device__ __forceinline__ void ldm_x4(uint32_t* r, uint32_t addr) {
    asm volatile("ldmatrix.sync.aligned.m8n8.x4.shared.b16 {%0,%1,%2,%3}, [%4];"
                 : "=r"(r[0]), "=r"(r[1]), "=r"(r[2]), "=r"(r[3]) : "r"(addr));
}

static __device__ __forceinline__ void mma_bf16(float* d, const uint32_t* a,
                                                const uint32_t* b) {
    asm volatile(
        "mma.sync.aligned.m16n8k16.row.col.f32.bf16.bf16.f32 "
        "{%0,%1,%2,%3}, {%4,%5,%6,%7}, {%8,%9}, {%0,%1,%2,%3};"
        : "+f"(d[0]), "+f"(d[1]), "+f"(d[2]), "+f"(d[3])
        : "r"(a[0]), "r"(a[1]), "r"(a[2]), "r"(a[3]), "r"(b[0]), "r"(b[1]));
}

// ============================================================================
// Kernel
// ============================================================================
__global__ void __launch_bounds__(NTHREADS, 1)
neural_ode_kernel(const float* __restrict__ x0, const float* __restrict__ W1,
                  const float* __restrict__ b1, const float* __restrict__ W2,
                  const float* __restrict__ b2, const float* __restrict__ W3,
                  const float* __restrict__ b3, const float* __restrict__ dts,
                  float* __restrict__ out, int T)
{
    extern __shared__ char smem[];
    const uint32_t sb = smem_u32(smem);
    const int tid = threadIdx.x;
    const int wid = tid >> 5;
    const int lane = tid & 31;
    const int nb = wid * 32;
    const uint32_t q = (uint32_t)(lane >> 3), r = (uint32_t)(lane & 7);

    // ---- stage W2 (permanent) + W1 (transient at H1_OFF) + biases ----
    for (int i = tid; i < HID * HID; i += NTHREADS) {            // W2 [256k][256n]
        int k = i >> 8, n = i & 255;
        *reinterpret_cast<__nv_bfloat16*>(smem + W2_OFF + (uint32_t)n * W2_STR
                                          + (uint32_t)k * 2u) = __float2bfloat16(W2[i]);
    }
    for (int i = tid; i < STATE * HID; i += NTHREADS) {          // W1 [64k][256n]
        int k = i >> 8, n = i & 255;
        *reinterpret_cast<__nv_bfloat16*>(smem + H1_OFF + (uint32_t)n * W1_STR
                                          + (uint32_t)k * 2u) = __float2bfloat16(W1[i]);
    }
    float* b1s = reinterpret_cast<float*>(smem + B1S_OFF);
    float* b2s = reinterpret_cast<float*>(smem + B2S_OFF);
    float* b3s = reinterpret_cast<float*>(smem + B3S_OFF);
    for (int i = tid; i < HID; i += NTHREADS) { b1s[i] = b1[i]; b2s[i] = b2[i]; }
    for (int i = tid; i < STATE; i += NTHREADS) b3s[i] = b3[i];
    __syncthreads();

    // ---- preload W1 B-fragments: warp w, n-cols 32w..32w+32, all K=64 ----
    uint32_t b1r[32];   // [ks*8 + {b01[0..3], b23[0..3]}]
    {
        const uint32_t bb = sb + H1_OFF
                          + (uint32_t)(nb + (int)((q >> 1) * 8) + (int)r) * W1_STR
                          + (q & 1) * 16u;
        #pragma unroll
        for (int ks = 0; ks < 4; ks++) {
            ldm_x4(b1r + ks * 8,     bb + (uint32_t)ks * 32u);
            ldm_x4(b1r + ks * 8 + 4, bb + 16u * W1_STR + (uint32_t)ks * 32u);
        }
    }
    __syncthreads();

    // ---- stage W3^T [64 n3][256 k] transient at H1_OFF; init x/traj/XB ----
    for (int i = tid; i < HID * STATE; i += NTHREADS) {
        int k = i >> 6, n = i & 63;
        *reinterpret_cast<__nv_bfloat16*>(smem + H1_OFF + (uint32_t)n * W3_STR
                                          + (uint32_t)k * 2u) = __float2bfloat16(W3[i]);
    }

    const float dtdt = dts[0] * 0.01f;
    const int nsteps = T - 1;
    const int gb = blockIdx.x * MROWS;
    const int colb = wid * 8 + 2 * (lane & 3);

    float xr[2][4];   // D-fragment-resident fp32 state
    #pragma unroll
    for (int mt = 0; mt < 2; mt++)
        #pragma unroll
        for (int half = 0; half < 2; half++) {
            const int row = mt * 16 + half * 8 + (lane >> 2);
            const float2 v = *reinterpret_cast<const float2*>(
                x0 + (size_t)(gb + row) * STATE + colb);
            xr[mt][2 * half] = v.x;
            xr[mt][2 * half + 1] = v.y;
            *reinterpret_cast<float2*>(
                out + (size_t)(gb + row) * T * STATE + colb) = v;
            *reinterpret_cast<uint32_t*>(smem + XB_OFF + (uint32_t)row * XB_STR
                + (uint32_t)colb * 2u) = pack_bf16x2(v.x, v.y);
        }
    __syncthreads();

    // ---- preload W3 B-fragments: warp w's k-slice [32w,32w+32), all 64 n3 ----
    uint32_t b3r[32];   // [nt3*4 + {kc0: 0,1 | kc1: 2,3}]
    {
        const uint32_t bb = sb + H1_OFF + r * W3_STR + (uint32_t)(wid * 64) + q * 16u;
        #pragma unroll
        for (int nt3 = 0; nt3 < 8; nt3++)
            ldm_x4(b3r + nt3 * 4, bb + (uint32_t)(nt3 * 8) * W3_STR);
    }
    __syncthreads();

    const uint32_t b2base = sb + W2_OFF
                          + (uint32_t)(nb + (int)((q >> 1) * 8) + (int)r) * W2_STR
                          + (q & 1) * 16u;
    const float bb3_0 = b3s[colb], bb3_1 = b3s[colb + 1];

    // ---- cache first KCACHE k-steps of W2 B-fragments (loop-invariant) ----
    uint32_t b2c[KCACHE * 8];
    #pragma unroll
    for (int ks = 0; ks < KCACHE; ks++) {
        ldm_x4(b2c + ks * 8,     b2base + (uint32_t)ks * 32u);
        ldm_x4(b2c + ks * 8 + 4, b2base + 16u * W2_STR + (uint32_t)ks * 32u);
    }

    for (int s = 0; s < nsteps; s++) {
        // ====== stage 1: H1 = tanh(X@W1+b1), B in regs, bf16x2 tanh ========
        {
            float acc[2][4][4];
            #pragma unroll
            for (int i = 0; i < 2; i++)
                #pragma unroll
                for (int j = 0; j < 4; j++)
                    #pragma unroll
                    for (int c = 0; c < 4; c++) acc[i][j][c] = 0.f;

            const uint32_t a_base = sb + XB_OFF + (uint32_t)(lane & 15) * XB_STR
                                  + (uint32_t)(lane >> 4) * 16u;
            #pragma unroll
            for (int ks = 0; ks < 4; ks++) {
                uint32_t a0[4], a1[4];
                ldm_x4(a0, a_base + (uint32_t)ks * 32u);
                ldm_x4(a1, a_base + 16u * XB_STR + (uint32_t)ks * 32u);
                const uint32_t* bk = b1r + ks * 8;
                mma_bf16(acc[0][0], a0, bk + 0);
                mma_bf16(acc[0][1], a0, bk + 2);
                mma_bf16(acc[0][2], a0, bk + 4);
                mma_bf16(acc[0][3], a0, bk + 6);
                mma_bf16(acc[1][0], a1, bk + 0);
                mma_bf16(acc[1][1], a1, bk + 2);
                mma_bf16(acc[1][2], a1, bk + 4);
                mma_bf16(acc[1][3], a1, bk + 6);
            }
            #pragma unroll
            for (int mt = 0; mt < 2; mt++) {
                const int row = mt * 16 + (lane >> 2);
                #pragma unroll
                for (int nt = 0; nt < 4; nt++) {
                    const int col = nb + nt * 8 + 2 * (lane & 3);
                    const float c0 = b1s[col], c1 = b1s[col + 1];
                    uint32_t t01 = tanh_bf16x2(pack_bf16x2(acc[mt][nt][0] + c0,
                                                           acc[mt][nt][1] + c1));
                    uint32_t t23 = tanh_bf16x2(pack_bf16x2(acc[mt][nt][2] + c0,
                                                           acc[mt][nt][3] + c1));
                    *reinterpret_cast<uint32_t*>(smem + H1_OFF + (uint32_t)row * H_STR
                        + (uint32_t)col * 2u) = t01;
                    *reinterpret_cast<uint32_t*>(smem + H1_OFF + (uint32_t)(row + 8) * H_STR
                        + (uint32_t)col * 2u) = t23;
                }
            }
        }

        // pre-barrier prefetch of the first two UNCACHED B k-steps (W2 static)
        uint32_t bcA[8], bcB[8];
        ldm_x4(bcA,     b2base + (uint32_t)KCACHE * 32u);
        ldm_x4(bcA + 4, b2base + 16u * W2_STR + (uint32_t)KCACHE * 32u);
        ldm_x4(bcB,     b2base + (uint32_t)(KCACHE + 1) * 32u);
        ldm_x4(bcB + 4, b2base + 16u * W2_STR + (uint32_t)(KCACHE + 1) * 32u);
        __syncthreads();                              // H1 visible

        // ====== stage 2: acc2 = H1 @ W2 (K=256), ping-pong, zero copies ====
        float acc2[2][4][4];
        #pragma unroll
        for (int i = 0; i < 2; i++)
            #pragma unroll
            for (int j = 0; j < 4; j++)
                #pragma unroll
                for (int c = 0; c < 4; c++) acc2[i][j][c] = 0.f;
        {
            const uint32_t a_base = sb + H1_OFF + (uint32_t)(lane & 15) * H_STR
                                  + (uint32_t)(lane >> 4) * 16u;
            uint32_t acA[8], acB[8];
            ldm_x4(acA,     a_base);
            ldm_x4(acA + 4, a_base + 16u * H_STR);
            #pragma unroll
            for (int ks = 0; ks < 16; ks += 2) {
                // ---- even sub-iter: consume acA / B(ks) ----
                if (ks + 1 < 16) {
                    ldm_x4(acB,     a_base + (uint32_t)(ks + 1) * 32u);
                    ldm_x4(acB + 4, a_base + 16u * H_STR + (uint32_t)(ks + 1) * 32u);
                    if (ks + 1 >= KCACHE + 2) {      // bcB slot (odd ks), 6/7 pre-done
                        ldm_x4(bcB,     b2base + (uint32_t)(ks + 1) * 32u);
                        ldm_x4(bcB + 4, b2base + 16u * W2_STR + (uint32_t)(ks + 1) * 32u);
                    }
                }
                {
                    const uint32_t* bp = (ks < KCACHE) ? (b2c + ks * 8) : bcA;
                    mma_bf16(acc2[0][0], acA,     bp + 0);
                    mma_bf16(acc2[0][1], acA,     bp + 2);
                    mma_bf16(acc2[0][2], acA,     bp + 4);
                    mma_bf16(acc2[0][3], acA,     bp + 6);
                    mma_bf16(acc2[1][0], acA + 4, bp + 0);
                    mma_bf16(acc2[1][1], acA + 4, bp + 2);
                    mma_bf16(acc2[1][2], acA + 4, bp + 4);
                    mma_bf16(acc2[1][3], acA + 4, bp + 6);
                }
                // ---- odd sub-iter: consume acB / B(ks+1) ----
                if (ks + 2 < 16) {
                    ldm_x4(acA,     a_base + (uint32_t)(ks + 2) * 32u);
                    ldm_x4(acA + 4, a_base + 16u * H_STR + (uint32_t)(ks + 2) * 32u);
                    if (ks + 2 >= KCACHE + 2) {      // bcA slot (even ks)
                        ldm_x4(bcA,     b2base + (uint32_t)(ks + 2) * 32u);
                        ldm_x4(bcA + 4, b2base + 16u * W2_STR + (uint32_t)(ks + 2) * 32u);
                    }
                }
                {
                    const uint32_t* bp = (ks + 1 < KCACHE) ? (b2c + (ks + 1) * 8) : bcB;
                    mma_bf16(acc2[0][0], acB,     bp + 0);
                    mma_bf16(acc2[0][1], acB,     bp + 2);
                    mma_bf16(acc2[0][2], acB,     bp + 4);
                    mma_bf16(acc2[0][3], acB,     bp + 6);
                    mma_bf16(acc2[1][0], acB + 4, bp + 0);
                    mma_bf16(acc2[1][1], acB + 4, bp + 2);
                    mma_bf16(acc2[1][2], acB + 4, bp + 4);
                    mma_bf16(acc2[1][3], acB + 4, bp + 6);
                }
            }
        }

        // ======= fused stage 3: bf16x2 tanh -> A-frags -> partial F ========
        {
            uint32_t p[2][4][2];   // tanh(H2) packed bf16x2; [mt][nt][half-row]
            #pragma unroll
            for (int mt = 0; mt < 2; mt++)
                #pragma unroll
                for (int nt = 0; nt < 4; nt++) {
                    const int col = nb + nt * 8 + 2 * (lane & 3);
                    const float c0 = b2s[col], c1 = b2s[col + 1];
                    p[mt][nt][0] = tanh_bf16x2(pack_bf16x2(acc2[mt][nt][0] + c0,
                                                           acc2[mt][nt][1] + c1));
                    p[mt][nt][1] = tanh_bf16x2(pack_bf16x2(acc2[mt][nt][2] + c0,
                                                           acc2[mt][nt][3] + c1));
                }

            const uint32_t rbo = RED_OFF + (uint32_t)wid * RW_STR
                               + (uint32_t)(2 * (lane & 3)) * 2u
                               + (uint32_t)(lane >> 2) * RROW_STR;

            #pragma unroll
            for (int mt = 0; mt < 2; mt++) {
                float f3[8][4];
                #pragma unroll
                for (int nt3 = 0; nt3 < 8; nt3++)
                    #pragma unroll
                    for (int c = 0; c < 4; c++) f3[nt3][c] = 0.f;
                #pragma unroll
                for (int kc = 0; kc < 2; kc++) {
                    uint32_t af[4] = { p[mt][2 * kc][0], p[mt][2 * kc][1],
                                       p[mt][2 * kc + 1][0], p[mt][2 * kc + 1][1] };
                    #pragma unroll
                    for (int nt3 = 0; nt3 < 8; nt3++)
                        mma_bf16(f3[nt3], af, b3r + nt3 * 4 + kc * 2);
                }
                #pragma unroll
                for (int nt3 = 0; nt3 < 8; nt3++) {
                    const uint32_t cb = (uint32_t)(nt3 * 8) * 2u
                                      + (uint32_t)(mt * 16) * RROW_STR;
                    *reinterpret_cast<uint32_t*>(smem + rbo + cb)
                        = pack_bf16x2(f3[nt3][0], f3[nt3][1]);
                    *reinterpret_cast<uint32_t*>(smem + rbo + cb + 8u * RROW_STR)
                        = pack_bf16x2(f3[nt3][2], f3[nt3][3]);
                }
            }
        }
        __syncthreads();                              // partials ready

        // ====== reduce 8 partials (bf16x2 tree) + Euler + traj + XB ========
        #pragma unroll
        for (int mt = 0; mt < 2; mt++)
            #pragma unroll
            for (int half = 0; half < 2; half++) {
                const int row = mt * 16 + half * 8 + (lane >> 2);
                const uint32_t a0 = RED_OFF + (uint32_t)row * RROW_STR
                                  + (uint32_t)colb * 2u;
                uint32_t u[8];
                #pragma unroll
                for (int w2 = 0; w2 < 8; w2++)
                    u[w2] = *reinterpret_cast<const uint32_t*>(
                        smem + a0 + (uint32_t)w2 * RW_STR);
                uint32_t t0 = hadd2_bf16(hadd2_bf16(u[0], u[1]),
                                         hadd2_bf16(u[2], u[3]));
                uint32_t t1 = hadd2_bf16(hadd2_bf16(u[4], u[5]),
                                         hadd2_bf16(u[6], u[7]));
                float s0 = bf16lo(t0) + bf16lo(t1);
                float s1 = bf16hi(t0) + bf16hi(t1);
                float xa = fmaf(s0 + bb3_0, dtdt, xr[mt][2 * half]);
                float xb = fmaf(s1 + bb3_1, dtdt, xr[mt][2 * half + 1]);
                xr[mt][2 * half] = xa;
                xr[mt][2 * half + 1] = xb;
                *reinterpret_cast<uint32_t*>(smem + XB_OFF + (uint32_t)row * XB_STR
                    + (uint32_t)colb * 2u) = pack_bf16x2(xa, xb);
                *reinterpret_cast<float2*>(
                    out + ((size_t)(gb + row) * T + (size_t)(s + 1)) * STATE + colb)
                    = make_float2(xa, xb);
            }
        __syncthreads();                              // XB ready, RED consumed
    }
}

// ============================================================================
// Launch
// ============================================================================
extern "C" void kernel_launch(void* const* d_in, const int* in_sizes, int n_in,
                              void* d_out, int out_size) {
    const float* x0  = (const float*)d_in[0];
    const float* W1  = (const float*)d_in[1];
    const float* b1  = (const float*)d_in[2];
    const float* W2  = (const float*)d_in[3];
    const float* b2  = (const float*)d_in[4];
    const float* W3  = (const float*)d_in[5];
    const float* b3  = (const float*)d_in[6];
    const float* dts = (const float*)d_in[7];
    float* out = (float*)d_out;

    const int T = out_size / (BATCHN * STATE);   // steps + 1

    cudaFuncSetAttribute(neural_ode_kernel,
                         cudaFuncAttributeMaxDynamicSharedMemorySize, SMEM_BYTES);
    neural_ode_kernel<<<NCTAS, NTHREADS, SMEM_BYTES>>>(
        x0, W1, b1, W2, b2, W3, b3, dts, out, T);
}